// round 1
// baseline (speedup 1.0000x reference)
#include <cuda_runtime.h>

#define D 128
#define TQ 128
#define TK 64
#define NTHREADS 256
#define NGLOBAL 100
#define LPRE 2048

// shared memory layout (in floats)
#define QS_OFF 0
#define KS_OFF (TQ * D)                    // 16384
#define VS_OFF (KS_OFF + TK * D)           // 24576
#define PT_OFF (VS_OFF + TK * D)           // 32768
#define PT_STRIDE (TQ + 1)                 // 129 (odd -> conflict-free scalar writes)
#define SMEM_FLOATS (PT_OFF + TK * PT_STRIDE)

// fast exp2 for x <= 0 (poly deg-6, rel err ~1e-5). Handles -1e30 sentinel -> ~0.
__device__ __forceinline__ float fexp2(float x) {
    x = fmaxf(x, -126.0f);
    int ni = __float2int_rd(x);
    float f = x - (float)ni;
    float p = 1.54035304e-4f;
    p = fmaf(p, f, 1.33335581e-3f);
    p = fmaf(p, f, 9.61812911e-3f);
    p = fmaf(p, f, 5.55041087e-2f);
    p = fmaf(p, f, 2.40226507e-1f);
    p = fmaf(p, f, 6.93147181e-1f);
    p = fmaf(p, f, 1.0f);
    return __int_as_float(__float_as_int(p) + (ni << 23));
}

__global__ void __launch_bounds__(NTHREADS, 1)
lminf_kernel(const float* __restrict__ Q, const float* __restrict__ K,
             const float* __restrict__ V, float* __restrict__ O, int S) {
    extern __shared__ float sm[];
    float* Qs = sm + QS_OFF;
    float* Ks = sm + KS_OFF;
    float* Vs = sm + VS_OFF;
    float* Pt = sm + PT_OFF;

    const int b  = blockIdx.y;
    const int q0 = blockIdx.x * TQ;
    const int tid = threadIdx.x;
    const int tq = tid >> 4;   // 0..15 : query group (rows tq + 16*m)
    const int tk = tid & 15;   // 0..15 : key group (keys tk + 16*r) / dims (8*tk..8*tk+7)

    const float* Qg = Q + (size_t)b * S * D;
    const float* Kg = K + (size_t)b * S * D;
    const float* Vg = V + (size_t)b * S * D;

    const float QSCALE = 0.0883883476f * 1.44269504089f;  // 1/sqrt(128) * log2(e)
    const float LOG2E  = 1.44269504089f;

    // ---- load Q tile into swizzled smem, pre-scaled ----
    {
        const float4* src = (const float4*)(Qg + (size_t)q0 * D);
        float4* dst = (float4*)Qs;
        #pragma unroll
        for (int it = 0; it < (TQ * 32) / NTHREADS; it++) {
            int idx = tid + it * NTHREADS;
            int row = idx >> 5, d4 = idx & 31;
            float4 val = src[idx];
            val.x *= QSCALE; val.y *= QSCALE; val.z *= QSCALE; val.w *= QSCALE;
            dst[row * 32 + (d4 ^ (row & 7))] = val;
        }
    }

    float acc[8][8];
    float mrow[8], lrow[8];
    #pragma unroll
    for (int m = 0; m < 8; m++) {
        mrow[m] = -1e30f; lrow[m] = 0.0f;
        #pragma unroll
        for (int c = 0; c < 8; c++) acc[m][c] = 0.0f;
    }

    const int xq = tq & 7;
    const int xk = tk & 7;
    const float4* Qs4 = (const float4*)Qs;
    const float4* Ks4 = (const float4*)Ks;
    const float4* Vs4 = (const float4*)Vs;

    const int kend = q0 + TQ;
    for (int k0 = 0; k0 < kend; k0 += TK) {
        // skip tiles entirely outside global sinks and all local windows of this block
        if (k0 >= NGLOBAL && (k0 + TK) <= (q0 - LPRE + 1)) continue;

        __syncthreads();   // previous tile's PV done reading Vs
        // ---- load K (swizzled) + V (plain) tiles ----
        {
            const float4* ksrc = (const float4*)(Kg + (size_t)k0 * D);
            const float4* vsrc = (const float4*)(Vg + (size_t)k0 * D);
            float4* kdst = (float4*)Ks;
            float4* vdst = (float4*)Vs;
            #pragma unroll
            for (int it = 0; it < (TK * 32) / NTHREADS; it++) {
                int idx = tid + it * NTHREADS;
                int row = idx >> 5, d4 = idx & 31;
                kdst[row * 32 + (d4 ^ (row & 7))] = ksrc[idx];
                vdst[idx] = vsrc[idx];
            }
        }
        __syncthreads();

        // ---- scores: 8q x 4k per thread ----
        float s[8][4];
        #pragma unroll
        for (int m = 0; m < 8; m++)
            #pragma unroll
            for (int r = 0; r < 4; r++) s[m][r] = 0.0f;

        #pragma unroll 4
        for (int d4 = 0; d4 < 32; d4++) {
            float4 kv[4];
            int ck = d4 ^ xk;
            int cq = d4 ^ xq;
            #pragma unroll
            for (int r = 0; r < 4; r++)
                kv[r] = Ks4[(tk + 16 * r) * 32 + ck];
            #pragma unroll
            for (int m = 0; m < 8; m++) {
                float4 qv = Qs4[(tq + 16 * m) * 32 + cq];
                #pragma unroll
                for (int r = 0; r < 4; r++) {
                    s[m][r] = fmaf(qv.x, kv[r].x, s[m][r]);
                    s[m][r] = fmaf(qv.y, kv[r].y, s[m][r]);
                    s[m][r] = fmaf(qv.z, kv[r].z, s[m][r]);
                    s[m][r] = fmaf(qv.w, kv[r].w, s[m][r]);
                }
            }
        }

        // ---- mask + bias + online softmax (log2 domain) ----
        #pragma unroll
        for (int m = 0; m < 8; m++) {
            int i = q0 + tq + 16 * m;
            float val[4];
            float tmax = -1e30f;
            #pragma unroll
            for (int r = 0; r < 4; r++) {
                int j = k0 + tk + 16 * r;
                bool allowed = (j <= i) && ((j < NGLOBAL) || (j >= i - (LPRE - 1)));
                float vv = allowed ? fmaf((float)(j - i), LOG2E, s[m][r]) : -1e30f;
                val[r] = vv;
                tmax = fmaxf(tmax, vv);
            }
            #pragma unroll
            for (int off = 8; off >= 1; off >>= 1)
                tmax = fmaxf(tmax, __shfl_xor_sync(0xffffffffu, tmax, off, 16));

            float mnew  = fmaxf(mrow[m], tmax);
            float scale = fexp2(mrow[m] - mnew);
            float psum = 0.0f;
            #pragma unroll
            for (int r = 0; r < 4; r++) {
                float p = fexp2(val[r] - mnew);
                psum += p;
                Pt[(tk + 16 * r) * PT_STRIDE + (tq + 16 * m)] = p;
            }
            #pragma unroll
            for (int off = 8; off >= 1; off >>= 1)
                psum += __shfl_xor_sync(0xffffffffu, psum, off, 16);

            lrow[m] = lrow[m] * scale + psum;
            mrow[m] = mnew;
            #pragma unroll
            for (int c = 0; c < 8; c++) acc[m][c] *= scale;
        }
        __syncwarp();   // P exchange is within a half-warp only

        // ---- PV: acc[8q][8d] += P * V ----
        #pragma unroll 4
        for (int key = 0; key < TK; key++) {
            float4 v0 = Vs4[key * 32 + tk * 2];
            float4 v1 = Vs4[key * 32 + tk * 2 + 1];
            const float* prow = Pt + key * PT_STRIDE + tq;
            #pragma unroll
            for (int m = 0; m < 8; m++) {
                float p = prow[16 * m];
                acc[m][0] = fmaf(p, v0.x, acc[m][0]);
                acc[m][1] = fmaf(p, v0.y, acc[m][1]);
                acc[m][2] = fmaf(p, v0.z, acc[m][2]);
                acc[m][3] = fmaf(p, v0.w, acc[m][3]);
                acc[m][4] = fmaf(p, v1.x, acc[m][4]);
                acc[m][5] = fmaf(p, v1.y, acc[m][5]);
                acc[m][6] = fmaf(p, v1.z, acc[m][6]);
                acc[m][7] = fmaf(p, v1.w, acc[m][7]);
            }
        }
    }

    // ---- epilogue: O = acc / l ----
    #pragma unroll
    for (int m = 0; m < 8; m++) {
        float inv = 1.0f / lrow[m];
        int i = q0 + tq + 16 * m;
        float4* dst = (float4*)(O + ((size_t)b * S + i) * D);
        float4 o0, o1;
        o0.x = acc[m][0] * inv; o0.y = acc[m][1] * inv;
        o0.z = acc[m][2] * inv; o0.w = acc[m][3] * inv;
        o1.x = acc[m][4] * inv; o1.y = acc[m][5] * inv;
        o1.z = acc[m][6] * inv; o1.w = acc[m][7] * inv;
        dst[tk * 2]     = o0;
        dst[tk * 2 + 1] = o1;
    }
}

extern "C" void kernel_launch(void* const* d_in, const int* in_sizes, int n_in,
                              void* d_out, int out_size) {
    const float* q = (const float*)d_in[0];
    const float* k = (const float*)d_in[1];
    const float* v = (const float*)d_in[2];
    float* o = (float*)d_out;

    const int B = 2;
    const int S = in_sizes[0] / (B * D);   // 8192

    size_t smem_bytes = (size_t)SMEM_FLOATS * sizeof(float);  // ~160 KB
    cudaFuncSetAttribute(lminf_kernel, cudaFuncAttributeMaxDynamicSharedMemorySize,
                         (int)smem_bytes);

    dim3 grid(S / TQ, B);
    lminf_kernel<<<grid, NTHREADS, smem_bytes>>>(q, k, v, o, S);
}